// round 4
// baseline (speedup 1.0000x reference)
#include <cuda_runtime.h>
#include <math.h>

#define BB 2
#define SS 2048
#define EE 2048
#define HH 16
#define HDD 64
#define DVV 128
#define CHN 32
#define MTOKS 4096
#define LAMBDA_INIT_F 0.78360576653162446f

// ---------------- scratch (no allocs allowed) ----------------
__device__ float g_q[(size_t)MTOKS * EE];
__device__ float g_k[(size_t)MTOKS * EE];
__device__ float g_v[(size_t)MTOKS * EE];
__device__ float g_o1[(size_t)MTOKS * EE];
__device__ float g_o2[(size_t)MTOKS * EE];
__device__ float g_attn[(size_t)MTOKS * EE];
__device__ float g_lam;

// ---------------- GEMM: C[M,N] = A[M,K] * W[N,K]^T ----------------
#define GBM 128
#define GBN 128
#define GBK 16

__global__ __launch_bounds__(256, 2) void gemm_nt(
    const float* __restrict__ A, const float* __restrict__ W,
    float* __restrict__ C, int M, int N, int K)
{
    __shared__ float As[GBK][GBM + 4];
    __shared__ float Bs[GBK][GBN + 4];

    const int tid = threadIdx.x;
    const int tx = tid & 15;
    const int ty = tid >> 4;
    const int m0 = blockIdx.y * GBM;
    const int n0 = blockIdx.x * GBN;

    const int lr = tid >> 2;        // 0..63
    const int lc = (tid & 3) * 4;   // 0,4,8,12

    const float* Ap = A + (size_t)(m0 + lr) * K + lc;
    const float* Wp = W + (size_t)(n0 + lr) * K + lc;

    float acc[8][8];
    #pragma unroll
    for (int i = 0; i < 8; i++)
        #pragma unroll
        for (int j = 0; j < 8; j++) acc[i][j] = 0.f;

    float4 pa0 = *(const float4*)(Ap);
    float4 pa1 = *(const float4*)(Ap + (size_t)64 * K);
    float4 pb0 = *(const float4*)(Wp);
    float4 pb1 = *(const float4*)(Wp + (size_t)64 * K);

    for (int kt = 0; kt < K; kt += GBK) {
        As[lc + 0][lr] = pa0.x; As[lc + 1][lr] = pa0.y;
        As[lc + 2][lr] = pa0.z; As[lc + 3][lr] = pa0.w;
        As[lc + 0][lr + 64] = pa1.x; As[lc + 1][lr + 64] = pa1.y;
        As[lc + 2][lr + 64] = pa1.z; As[lc + 3][lr + 64] = pa1.w;
        Bs[lc + 0][lr] = pb0.x; Bs[lc + 1][lr] = pb0.y;
        Bs[lc + 2][lr] = pb0.z; Bs[lc + 3][lr] = pb0.w;
        Bs[lc + 0][lr + 64] = pb1.x; Bs[lc + 1][lr + 64] = pb1.y;
        Bs[lc + 2][lr + 64] = pb1.z; Bs[lc + 3][lr + 64] = pb1.w;
        __syncthreads();

        if (kt + GBK < K) {
            pa0 = *(const float4*)(Ap + kt + GBK);
            pa1 = *(const float4*)(Ap + (size_t)64 * K + kt + GBK);
            pb0 = *(const float4*)(Wp + kt + GBK);
            pb1 = *(const float4*)(Wp + (size_t)64 * K + kt + GBK);
        }

        #pragma unroll
        for (int kk = 0; kk < GBK; kk++) {
            float4 a0 = *(const float4*)&As[kk][ty * 8];
            float4 a1 = *(const float4*)&As[kk][ty * 8 + 4];
            float4 b0 = *(const float4*)&Bs[kk][tx * 8];
            float4 b1 = *(const float4*)&Bs[kk][tx * 8 + 4];
            float ar[8] = {a0.x, a0.y, a0.z, a0.w, a1.x, a1.y, a1.z, a1.w};
            float br[8] = {b0.x, b0.y, b0.z, b0.w, b1.x, b1.y, b1.z, b1.w};
            #pragma unroll
            for (int i = 0; i < 8; i++)
                #pragma unroll
                for (int j = 0; j < 8; j++)
                    acc[i][j] = fmaf(ar[i], br[j], acc[i][j]);
        }
        __syncthreads();
    }

    #pragma unroll
    for (int i = 0; i < 8; i++) {
        float* Cp = C + (size_t)(m0 + ty * 8 + i) * N + n0 + tx * 8;
        float4 v0 = make_float4(acc[i][0], acc[i][1], acc[i][2], acc[i][3]);
        float4 v1 = make_float4(acc[i][4], acc[i][5], acc[i][6], acc[i][7]);
        *(float4*)(Cp) = v0;
        *(float4*)(Cp + 4) = v1;
    }
}

// ---------------- RoPE (interleaved pairs, in place on q and k) ----------------
__global__ void rope_kernel(float* __restrict__ q, float* __restrict__ k)
{
    int idx = blockIdx.x * blockDim.x + threadIdx.x;
    const int total = MTOKS * CHN * (HDD / 2);
    if (idx >= total) return;
    int i = idx & 31;             // rotation pair index (0..31)
    int ch = (idx >> 5) & 31;     // 2H channel
    int tok = idx >> 10;          // b*S + t
    int t = tok & (SS - 1);
    float ang = (float)(1.0 / pow(10000.0, (double)i / (double)(HDD / 2 - 1)));
    float fr = (float)t * ang;
    float sn, cs;
    sincosf(fr, &sn, &cs);
    size_t base = (size_t)tok * EE + ch * HDD + 2 * i;
    float xe = q[base], xo = q[base + 1];
    q[base]     = xe * cs - xo * sn;
    q[base + 1] = xe * sn + xo * cs;
    xe = k[base]; xo = k[base + 1];
    k[base]     = xe * cs - xo * sn;
    k[base + 1] = xe * sn + xo * cs;
}

// ---------------- lambda scalar ----------------
__global__ void lambda_kernel(const float* __restrict__ lq1, const float* __restrict__ lk1,
                              const float* __restrict__ lq2, const float* __restrict__ lk2)
{
    int lane = threadIdx.x;
    float s1 = lq1[lane] * lk1[lane] + lq1[lane + 32] * lk1[lane + 32];
    float s2 = lq2[lane] * lk2[lane] + lq2[lane + 32] * lk2[lane + 32];
    #pragma unroll
    for (int off = 16; off; off >>= 1) {
        s1 += __shfl_xor_sync(0xffffffffu, s1, off);
        s2 += __shfl_xor_sync(0xffffffffu, s2, off);
    }
    if (lane == 0) g_lam = expf(s1) - expf(s2) + LAMBDA_INIT_F;
}

// ---------------- flash-style attention (fp32), one (b,ch) per blockIdx.(y,z) ----------------
#define ABM 128
#define ABN 64
#define AD 64
#define ADV 128

struct AttnSmem {
    float Qs[AD][ABM + 4];   // transposed: [d][row]
    float Ks[AD][ABN + 4];   // transposed: [d][col]
    float Vs[ABN][ADV];      // [col][dv]
    float Ps[ABM][ABN + 4];  // [row][col]
};

__global__ __launch_bounds__(256, 1) void attn_kernel(
    const float* __restrict__ q, const float* __restrict__ k,
    const float* __restrict__ v, float* __restrict__ o1, float* __restrict__ o2)
{
    extern __shared__ __align__(16) char smem_raw[];
    AttnSmem* sm = (AttnSmem*)smem_raw;

    const int tid = threadIdx.x;
    const int tx = tid & 15;
    const int ty = tid >> 4;
    const int q0 = blockIdx.x * ABM;
    const int ch = blockIdx.y;    // 0..31 : channel in 2H dim; comp = ch&1, h = ch>>1
    const int b  = blockIdx.z;
    const int h = ch >> 1;
    float* obuf = (ch & 1) ? o2 : o1;

    const float* qbase = q + (size_t)(b * SS + q0) * EE + ch * HDD;
    const float* kbase = k + (size_t)b * SS * EE + ch * HDD;
    const float* vbase = v + (size_t)b * SS * EE + h * DVV;

    // Load Q tile transposed
    for (int it = tid; it < ABM * (AD / 4); it += 256) {
        int r = it >> 4;
        int d4 = (it & 15) * 4;
        float4 val = *(const float4*)(qbase + (size_t)r * EE + d4);
        sm->Qs[d4 + 0][r] = val.x;
        sm->Qs[d4 + 1][r] = val.y;
        sm->Qs[d4 + 2][r] = val.z;
        sm->Qs[d4 + 3][r] = val.w;
    }

    const float NEG_INF = __int_as_float(0xff800000);
    float m[8], l[8], o[8][8];
    #pragma unroll
    for (int i = 0; i < 8; i++) {
        m[i] = NEG_INF;
        l[i] = 0.f;
        #pragma unroll
        for (int j = 0; j < 8; j++) o[i][j] = 0.f;
    }

    const float scale = 0.125f;  // HD^-0.5

    for (int s0 = 0; s0 < SS; s0 += ABN) {
        __syncthreads();   // protect Ks/Vs/Ps from previous iteration readers
        for (int it = tid; it < ABN * (AD / 4); it += 256) {
            int c = it >> 4;
            int d4 = (it & 15) * 4;
            float4 val = *(const float4*)(kbase + (size_t)(s0 + c) * EE + d4);
            sm->Ks[d4 + 0][c] = val.x;
            sm->Ks[d4 + 1][c] = val.y;
            sm->Ks[d4 + 2][c] = val.z;
            sm->Ks[d4 + 3][c] = val.w;
        }
        for (int it = tid; it < ABN * (ADV / 4); it += 256) {
            int c = it >> 5;
            int cv4 = (it & 31) * 4;
            *(float4*)&sm->Vs[c][cv4] = *(const float4*)(vbase + (size_t)(s0 + c) * EE + cv4);
        }
        __syncthreads();

        // ---- scores: S = Q K^T ----
        float sacc[8][4];
        #pragma unroll
        for (int i = 0; i < 8; i++)
            #pragma unroll
            for (int j = 0; j < 4; j++) sacc[i][j] = 0.f;

        #pragma unroll 8
        for (int d = 0; d < AD; d++) {
            float4 qa = *(const float4*)&sm->Qs[d][ty * 8];
            float4 qb = *(const float4*)&sm->Qs[d][ty * 8 + 4];
            float4 kv = *(const float4*)&sm->Ks[d][tx * 4];
            float qr[8] = {qa.x, qa.y, qa.z, qa.w, qb.x, qb.y, qb.z, qb.w};
            float kr[4] = {kv.x, kv.y, kv.z, kv.w};
            #pragma unroll
            for (int i = 0; i < 8; i++)
                #pragma unroll
                for (int j = 0; j < 4; j++)
                    sacc[i][j] = fmaf(qr[i], kr[j], sacc[i][j]);
        }

        // ---- online softmax (rows shared by 16-lane groups) ----
        #pragma unroll
        for (int i = 0; i < 8; i++) {
            float mx = fmaxf(fmaxf(sacc[i][0], sacc[i][1]), fmaxf(sacc[i][2], sacc[i][3]));
            #pragma unroll
            for (int off = 8; off; off >>= 1)
                mx = fmaxf(mx, __shfl_xor_sync(0xffffffffu, mx, off));
            mx *= scale;
            float mn = fmaxf(m[i], mx);
            float alpha = __expf(m[i] - mn);
            float rs = 0.f;
            #pragma unroll
            for (int j = 0; j < 4; j++) {
                float p = __expf(sacc[i][j] * scale - mn);
                rs += p;
                sm->Ps[ty * 8 + i][tx * 4 + j] = p;
            }
            #pragma unroll
            for (int off = 8; off; off >>= 1)
                rs += __shfl_xor_sync(0xffffffffu, rs, off);
            l[i] = l[i] * alpha + rs;
            m[i] = mn;
            #pragma unroll
            for (int j = 0; j < 8; j++) o[i][j] *= alpha;
        }
        __syncthreads();

        // ---- O += P V ----
        #pragma unroll 4
        for (int c0 = 0; c0 < ABN; c0 += 4) {
            float4 pv[8];
            #pragma unroll
            for (int i = 0; i < 8; i++)
                pv[i] = *(const float4*)&sm->Ps[ty * 8 + i][c0];
            #pragma unroll
            for (int cc = 0; cc < 4; cc++) {
                float4 va = *(const float4*)&sm->Vs[c0 + cc][tx * 8];
                float4 vb = *(const float4*)&sm->Vs[c0 + cc][tx * 8 + 4];
                float vr[8] = {va.x, va.y, va.z, va.w, vb.x, vb.y, vb.z, vb.w};
                #pragma unroll
                for (int i = 0; i < 8; i++) {
                    float p = (cc == 0) ? pv[i].x : (cc == 1) ? pv[i].y
                             : (cc == 2) ? pv[i].z : pv[i].w;
                    #pragma unroll
                    for (int j = 0; j < 8; j++)
                        o[i][j] = fmaf(p, vr[j], o[i][j]);
                }
            }
        }
    }

    // ---- epilogue: normalize by l, write (b,t,h,dv) ----
    #pragma unroll
    for (int i = 0; i < 8; i++) {
        float inv = 1.f / l[i];
        float* op = obuf + ((size_t)(b * SS + q0 + ty * 8 + i) * HH + h) * DVV + tx * 8;
        float4 v0 = make_float4(o[i][0] * inv, o[i][1] * inv, o[i][2] * inv, o[i][3] * inv);
        float4 v1 = make_float4(o[i][4] * inv, o[i][5] * inv, o[i][6] * inv, o[i][7] * inv);
        *(float4*)op = v0;
        *(float4*)(op + 4) = v1;
    }
}

// ---------------- combine: diff + RMSnorm + gamma ----------------
__global__ void combine_kernel(const float* __restrict__ o1, const float* __restrict__ o2,
                               const float* __restrict__ gamma, float* __restrict__ attn)
{
    int gtid = blockIdx.x * blockDim.x + threadIdx.x;
    int wid = gtid >> 5;       // (b*S + t)*H + h
    int lane = gtid & 31;
    float lam = g_lam;
    const float* p1 = o1 + (size_t)wid * DVV + lane * 4;
    const float* p2 = o2 + (size_t)wid * DVV + lane * 4;
    float4 a = *(const float4*)p1;
    float4 c2 = *(const float4*)p2;
    float4 d;
    d.x = a.x - lam * c2.x;
    d.y = a.y - lam * c2.y;
    d.z = a.z - lam * c2.z;
    d.w = a.w - lam * c2.w;
    float ss = d.x * d.x + d.y * d.y + d.z * d.z + d.w * d.w;
    #pragma unroll
    for (int off = 16; off; off >>= 1)
        ss += __shfl_xor_sync(0xffffffffu, ss, off);
    float r = rsqrtf(ss * (1.0f / DVV) + 1e-5f);
    float4 g = *(const float4*)(gamma + lane * 4);
    float sc = r * (1.0f - LAMBDA_INIT_F);
    float* op = attn + (size_t)(wid / HH) * EE + (wid % HH) * DVV + lane * 4;
    float4 outv = make_float4(d.x * sc * g.x, d.y * sc * g.y, d.z * sc * g.z, d.w * sc * g.w);
    *(float4*)op = outv;
}

// ---------------- launcher ----------------
extern "C" void kernel_launch(void* const* d_in, const int* in_sizes, int n_in,
                              void* d_out, int out_size)
{
    (void)in_sizes; (void)n_in; (void)out_size;
    const float* x   = (const float*)d_in[0];
    const float* Wq  = (const float*)d_in[1];
    const float* Wk  = (const float*)d_in[2];
    const float* Wv  = (const float*)d_in[3];
    const float* Wo  = (const float*)d_in[4];
    const float* lq1 = (const float*)d_in[5];
    const float* lk1 = (const float*)d_in[6];
    const float* lq2 = (const float*)d_in[7];
    const float* lk2 = (const float*)d_in[8];
    const float* gam = (const float*)d_in[9];
    float* out = (float*)d_out;

    float *pq, *pk, *pv, *po1, *po2, *pattn;
    cudaGetSymbolAddress((void**)&pq, g_q);
    cudaGetSymbolAddress((void**)&pk, g_k);
    cudaGetSymbolAddress((void**)&pv, g_v);
    cudaGetSymbolAddress((void**)&po1, g_o1);
    cudaGetSymbolAddress((void**)&po2, g_o2);
    cudaGetSymbolAddress((void**)&pattn, g_attn);

    cudaFuncSetAttribute(attn_kernel, cudaFuncAttributeMaxDynamicSharedMemorySize,
                         (int)sizeof(AttnSmem));

    dim3 gg(EE / GBN, MTOKS / GBM);
    gemm_nt<<<gg, 256>>>(x, Wq, pq, MTOKS, EE, EE);
    gemm_nt<<<gg, 256>>>(x, Wk, pk, MTOKS, EE, EE);
    gemm_nt<<<gg, 256>>>(x, Wv, pv, MTOKS, EE, EE);

    const int rope_total = MTOKS * CHN * (HDD / 2);
    rope_kernel<<<rope_total / 256, 256>>>(pq, pk);
    lambda_kernel<<<1, 32>>>(lq1, lk1, lq2, lk2);

    attn_kernel<<<dim3(SS / ABM, CHN, BB), 256, sizeof(AttnSmem)>>>(pq, pk, pv, po1, po2);

    combine_kernel<<<(BB * SS * HH * 32) / 256, 256>>>(po1, po2, gam, pattn);

    gemm_nt<<<gg, 256>>>(pattn, Wo, out, MTOKS, EE, EE);
}

// round 12
// speedup vs baseline: 1.4506x; 1.4506x over previous
#include <cuda_runtime.h>
#include <cuda_bf16.h>
#include <cstdint>
#include <math.h>

#define BB 2
#define SS 2048
#define EE 2048
#define HH 16
#define HDD 64
#define DVV 128
#define CHN 32
#define MTOKS 4096
#define LAMBDA_INIT_F 0.78360576653162446f

// ---------------- scratch (no allocs allowed) ----------------
__device__ float g_q[(size_t)MTOKS * EE];
__device__ float g_k[(size_t)MTOKS * EE];
__device__ float g_v[(size_t)MTOKS * EE];
__device__ float g_o1[(size_t)MTOKS * EE];
__device__ float g_o2[(size_t)MTOKS * EE];
__device__ float g_attn[(size_t)MTOKS * EE];
__device__ float g_lam;

// ================= warp-level tensor core helpers (sm_80+ baseline PTX) =================
__device__ __forceinline__ uint32_t smem_u32(const void* p) {
    uint32_t a;
    asm("{ .reg .u64 t; cvta.to.shared.u64 t, %1; cvt.u32.u64 %0, t; }" : "=r"(a) : "l"(p));
    return a;
}

__device__ __forceinline__ void ldsm_x4(uint32_t& r0, uint32_t& r1, uint32_t& r2, uint32_t& r3,
                                        uint32_t addr) {
    asm volatile("ldmatrix.sync.aligned.m8n8.x4.shared.b16 {%0,%1,%2,%3}, [%4];"
                 : "=r"(r0), "=r"(r1), "=r"(r2), "=r"(r3) : "r"(addr));
}
__device__ __forceinline__ void ldsm_x2(uint32_t& r0, uint32_t& r1, uint32_t addr) {
    asm volatile("ldmatrix.sync.aligned.m8n8.x2.shared.b16 {%0,%1}, [%2];"
                 : "=r"(r0), "=r"(r1) : "r"(addr));
}

__device__ __forceinline__ void mma_bf16(float* c, const uint32_t* a, const uint32_t* b) {
    asm volatile(
        "mma.sync.aligned.m16n8k16.row.col.f32.bf16.bf16.f32 "
        "{%0,%1,%2,%3}, {%4,%5,%6,%7}, {%8,%9}, {%0,%1,%2,%3};"
        : "+f"(c[0]), "+f"(c[1]), "+f"(c[2]), "+f"(c[3])
        : "r"(a[0]), "r"(a[1]), "r"(a[2]), "r"(a[3]), "r"(b[0]), "r"(b[1]));
}

// =============== tensor-core GEMM: C[M,N] = A[M,K] @ W[N,K]^T ===============
// bf16 hi/lo split, 3 mma.sync per (m,n,k16) step. Block 128x128, Ktile 32, 8 warps.
#define GROWB 80                      // smem row stride bytes (32 bf16 = 64B, pad to 80)
#define GTILE (128 * GROWB)           // 10240 B per operand tile

__global__ __launch_bounds__(256, 1) void gemm_mma(
    const float* __restrict__ A, const float* __restrict__ W,
    float* __restrict__ C, int M, int N, int K)
{
    __shared__ __align__(128) char sm[4 * GTILE];   // AH, AL, BH, BL
    const uint32_t sb = smem_u32(sm);
    const uint32_t sAH = sb, sAL = sb + GTILE, sBH = sb + 2 * GTILE, sBL = sb + 3 * GTILE;

    const int tid = threadIdx.x;
    const int w = tid >> 5;
    const int lane = tid & 31;
    const int m0 = blockIdx.y * 128;
    const int n0 = blockIdx.x * 128;
    const int wm = (w >> 2) * 64;      // warp m offset within block: 0 or 64
    const int wn = (w & 3) * 32;       // warp n offset: 0,32,64,96

    float acc[4][4][4];
    #pragma unroll
    for (int i = 0; i < 4; i++)
        #pragma unroll
        for (int j = 0; j < 4; j++)
            #pragma unroll
            for (int r = 0; r < 4; r++) acc[i][j][r] = 0.f;

    // ldmatrix source addresses (row within 16/8-row frag, k-half)
    const int a_i = lane & 15, a_half = lane >> 4;       // A frag lanes
    const int b_i = lane & 7,  b_half = (lane >> 3) & 1; // B frag lanes (0..15 used)

    const int KT = K / 32;
    for (int kt = 0; kt < KT; kt++) {
        // ---- stage global loads in regs ----
        float4 ra[4], rb[4];
        #pragma unroll
        for (int j = 0; j < 4; j++) {
            int lin = tid + 256 * j;
            int r = lin >> 3;                 // 0..127
            int c = (lin & 7) * 4;            // float col 0..28
            ra[j] = *(const float4*)(A + (size_t)(m0 + r) * K + kt * 32 + c);
            rb[j] = *(const float4*)(W + (size_t)(n0 + r) * K + kt * 32 + c);
        }
        __syncthreads();   // previous iteration's compute finished
        #pragma unroll
        for (int j = 0; j < 4; j++) {
            int lin = tid + 256 * j;
            int r = lin >> 3;
            int cb = (lin & 7) * 8;           // byte col in row (bf16)
            float4 va = ra[j], vb = rb[j];
            __nv_bfloat16 ah0 = __float2bfloat16(va.x), ah1 = __float2bfloat16(va.y);
            __nv_bfloat16 ah2 = __float2bfloat16(va.z), ah3 = __float2bfloat16(va.w);
            __nv_bfloat16 al0 = __float2bfloat16(va.x - __bfloat162float(ah0));
            __nv_bfloat16 al1 = __float2bfloat16(va.y - __bfloat162float(ah1));
            __nv_bfloat16 al2 = __float2bfloat16(va.z - __bfloat162float(ah2));
            __nv_bfloat16 al3 = __float2bfloat16(va.w - __bfloat162float(ah3));
            __nv_bfloat16 bh0 = __float2bfloat16(vb.x), bh1 = __float2bfloat16(vb.y);
            __nv_bfloat16 bh2 = __float2bfloat16(vb.z), bh3 = __float2bfloat16(vb.w);
            __nv_bfloat16 bl0 = __float2bfloat16(vb.x - __bfloat162float(bh0));
            __nv_bfloat16 bl1 = __float2bfloat16(vb.y - __bfloat162float(bh1));
            __nv_bfloat16 bl2 = __float2bfloat16(vb.z - __bfloat162float(bh2));
            __nv_bfloat16 bl3 = __float2bfloat16(vb.w - __bfloat162float(bh3));
            __nv_bfloat162 p;
            uint32_t u0, u1;
            char* base = sm + r * GROWB + cb;
            p.x = ah0; p.y = ah1; u0 = *(uint32_t*)&p;
            p.x = ah2; p.y = ah3; u1 = *(uint32_t*)&p;
            *(uint2*)(base) = make_uint2(u0, u1);
            p.x = al0; p.y = al1; u0 = *(uint32_t*)&p;
            p.x = al2; p.y = al3; u1 = *(uint32_t*)&p;
            *(uint2*)(base + GTILE) = make_uint2(u0, u1);
            p.x = bh0; p.y = bh1; u0 = *(uint32_t*)&p;
            p.x = bh2; p.y = bh3; u1 = *(uint32_t*)&p;
            *(uint2*)(base + 2 * GTILE) = make_uint2(u0, u1);
            p.x = bl0; p.y = bl1; u0 = *(uint32_t*)&p;
            p.x = bl2; p.y = bl3; u1 = *(uint32_t*)&p;
            *(uint2*)(base + 3 * GTILE) = make_uint2(u0, u1);
        }
        __syncthreads();

        // ---- tensor core compute: 2 k16 steps ----
        #pragma unroll
        for (int k16 = 0; k16 < 2; k16++) {
            uint32_t ah[4][4], al[4][4], bh[4][2], bl[4][2];
            const uint32_t kb = k16 * 32 + a_half * 16;
            #pragma unroll
            for (int mi = 0; mi < 4; mi++) {
                uint32_t row = wm + 16 * mi + a_i;
                ldsm_x4(ah[mi][0], ah[mi][1], ah[mi][2], ah[mi][3], sAH + row * GROWB + kb);
                ldsm_x4(al[mi][0], al[mi][1], al[mi][2], al[mi][3], sAL + row * GROWB + kb);
            }
            const uint32_t kbb = k16 * 32 + b_half * 16;
            #pragma unroll
            for (int ni = 0; ni < 4; ni++) {
                uint32_t row = wn + 8 * ni + b_i;
                ldsm_x2(bh[ni][0], bh[ni][1], sBH + row * GROWB + kbb);
                ldsm_x2(bl[ni][0], bl[ni][1], sBL + row * GROWB + kbb);
            }
            #pragma unroll
            for (int mi = 0; mi < 4; mi++)
                #pragma unroll
                for (int ni = 0; ni < 4; ni++) {
                    mma_bf16(acc[mi][ni], ah[mi], bh[ni]);
                    mma_bf16(acc[mi][ni], ah[mi], bl[ni]);
                    mma_bf16(acc[mi][ni], al[mi], bh[ni]);
                }
        }
    }

    // ---- epilogue ----
    const int cr = lane >> 2;           // 0..7
    const int cc = (lane & 3) * 2;      // 0,2,4,6
    #pragma unroll
    for (int mi = 0; mi < 4; mi++)
        #pragma unroll
        for (int ni = 0; ni < 4; ni++) {
            int row = m0 + wm + 16 * mi + cr;
            int col = n0 + wn + 8 * ni + cc;
            float* p0 = C + (size_t)row * N + col;
            p0[0] = acc[mi][ni][0];
            p0[1] = acc[mi][ni][1];
            float* p1 = C + (size_t)(row + 8) * N + col;
            p1[0] = acc[mi][ni][2];
            p1[1] = acc[mi][ni][3];
        }
}

// ---------------- RoPE (fp32, interleaved pairs, in place on q and k) ----------------
__global__ void rope_kernel(float* __restrict__ q, float* __restrict__ k)
{
    int idx = blockIdx.x * blockDim.x + threadIdx.x;
    const int total = MTOKS * CHN * (HDD / 2);
    if (idx >= total) return;
    int i = idx & 31;             // rotation pair index (0..31)
    int ch = (idx >> 5) & 31;     // 2H channel
    int tok = idx >> 10;          // b*S + t
    int t = tok & (SS - 1);
    // 10000^(-i/31) = exp2(-i * log2(10000)/31)
    float ang = exp2f((float)i * -0.4286358831467564f);
    float fr = (float)t * ang;
    float sn, cs;
    sincosf(fr, &sn, &cs);
    size_t base = (size_t)tok * EE + ch * HDD + 2 * i;
    float xe = q[base], xo = q[base + 1];
    q[base]     = xe * cs - xo * sn;
    q[base + 1] = xe * sn + xo * cs;
    xe = k[base]; xo = k[base + 1];
    k[base]     = xe * cs - xo * sn;
    k[base + 1] = xe * sn + xo * cs;
}

// ---------------- lambda scalar ----------------
__global__ void lambda_kernel(const float* __restrict__ lq1, const float* __restrict__ lk1,
                              const float* __restrict__ lq2, const float* __restrict__ lk2)
{
    int lane = threadIdx.x;
    float s1 = lq1[lane] * lk1[lane] + lq1[lane + 32] * lk1[lane + 32];
    float s2 = lq2[lane] * lk2[lane] + lq2[lane + 32] * lk2[lane + 32];
    #pragma unroll
    for (int off = 16; off; off >>= 1) {
        s1 += __shfl_xor_sync(0xffffffffu, s1, off);
        s2 += __shfl_xor_sync(0xffffffffu, s2, off);
    }
    if (lane == 0) g_lam = expf(s1) - expf(s2) + LAMBDA_INIT_F;
}

// ---------------- flash-style attention (fp32), one (b,ch) per blockIdx.(y,z) ----------------
#define ABM 128
#define ABN 64
#define AD 64
#define ADV 128

struct AttnSmem {
    float Qs[AD][ABM + 4];   // transposed: [d][row]
    float Ks[AD][ABN + 4];   // transposed: [d][col]
    float Vs[ABN][ADV];      // [col][dv]
    float Ps[ABM][ABN + 4];  // [row][col]
};

__global__ __launch_bounds__(256, 1) void attn_kernel(
    const float* __restrict__ q, const float* __restrict__ k,
    const float* __restrict__ v, float* __restrict__ o1, float* __restrict__ o2)
{
    extern __shared__ __align__(16) char smem_raw[];
    AttnSmem* sm = (AttnSmem*)smem_raw;

    const int tid = threadIdx.x;
    const int tx = tid & 15;
    const int ty = tid >> 4;
    const int q0 = blockIdx.x * ABM;
    const int ch = blockIdx.y;    // 0..31 : channel in 2H dim; comp = ch&1, h = ch>>1
    const int b  = blockIdx.z;
    const int h = ch >> 1;
    float* obuf = (ch & 1) ? o2 : o1;

    const float* qbase = q + (size_t)(b * SS + q0) * EE + ch * HDD;
    const float* kbase = k + (size_t)b * SS * EE + ch * HDD;
    const float* vbase = v + (size_t)b * SS * EE + h * DVV;

    // Load Q tile transposed
    for (int it = tid; it < ABM * (AD / 4); it += 256) {
        int r = it >> 4;
        int d4 = (it & 15) * 4;
        float4 val = *(const float4*)(qbase + (size_t)r * EE + d4);
        sm->Qs[d4 + 0][r] = val.x;
        sm->Qs[d4 + 1][r] = val.y;
        sm->Qs[d4 + 2][r] = val.z;
        sm->Qs[d4 + 3][r] = val.w;
    }

    const float NEG_INF = __int_as_float(0xff800000);
    float m[8], l[8], o[8][8];
    #pragma unroll
    for (int i = 0; i < 8; i++) {
        m[i] = NEG_INF;
        l[i] = 0.f;
        #pragma unroll
        for (int j = 0; j < 8; j++) o[i][j] = 0.f;
    }

    const float scale = 0.125f;  // HD^-0.5

    for (int s0 = 0; s0 < SS; s0 += ABN) {
        __syncthreads();   // protect Ks/Vs/Ps from previous iteration readers
        for (int it = tid; it < ABN * (AD / 4); it += 256) {
            int c = it >> 4;
            int d4 = (it & 15) * 4;
            float4 val = *(const float4*)(kbase + (size_t)(s0 + c) * EE + d4);
            sm->Ks[d4 + 0][c] = val.x;
            sm->Ks[d4 + 1][c] = val.y;
            sm->Ks[d4 + 2][c] = val.z;
            sm->Ks[d4 + 3][c] = val.w;
        }
        for (int it = tid; it < ABN * (ADV / 4); it += 256) {
            int c = it >> 5;
            int cv4 = (it & 31) * 4;
            *(float4*)&sm->Vs[c][cv4] = *(const float4*)(vbase + (size_t)(s0 + c) * EE + cv4);
        }
        __syncthreads();

        // ---- scores: S = Q K^T ----
        float sacc[8][4];
        #pragma unroll
        for (int i = 0; i < 8; i++)
            #pragma unroll
            for (int j = 0; j < 4; j++) sacc[i][j] = 0.f;

        #pragma unroll 8
        for (int d = 0; d < AD; d++) {
            float4 qa = *(const float4*)&sm->Qs[d][ty * 8];
            float4 qb = *(const float4*)&sm->Qs[d][ty * 8 + 4];
            float4 kv = *(const float4*)&sm->Ks[d][tx * 4];
            float qr[8] = {qa.x, qa.y, qa.z, qa.w, qb.x, qb.y, qb.z, qb.w};
            float kr[4] = {kv.x, kv.y, kv.z, kv.w};
            #pragma unroll
            for (int i = 0; i < 8; i++)
                #pragma unroll
                for (int j = 0; j < 4; j++)
                    sacc[i][j] = fmaf(qr[i], kr[j], sacc[i][j]);
        }

        // ---- online softmax (rows shared by 16-lane groups) ----
        #pragma unroll
        for (int i = 0; i < 8; i++) {
            float mx = fmaxf(fmaxf(sacc[i][0], sacc[i][1]), fmaxf(sacc[i][2], sacc[i][3]));
            #pragma unroll
            for (int off = 8; off; off >>= 1)
                mx = fmaxf(mx, __shfl_xor_sync(0xffffffffu, mx, off));
            mx *= scale;
            float mn = fmaxf(m[i], mx);
            float alpha = __expf(m[i] - mn);
            float rs = 0.f;
            #pragma unroll
            for (int j = 0; j < 4; j++) {
                float p = __expf(sacc[i][j] * scale - mn);
                rs += p;
                sm->Ps[ty * 8 + i][tx * 4 + j] = p;
            }
            #pragma unroll
            for (int off = 8; off; off >>= 1)
                rs += __shfl_xor_sync(0xffffffffu, rs, off);
            l[i] = l[i] * alpha + rs;
            m[i] = mn;
            #pragma unroll
            for (int j = 0; j < 8; j++) o[i][j] *= alpha;
        }
        __syncthreads();

        // ---- O += P V ----
        #pragma unroll 4
        for (int c0 = 0; c0 < ABN; c0 += 4) {
            float4 pv[8];
            #pragma unroll
            for (int i = 0; i < 8; i++)
                pv[i] = *(const float4*)&sm->Ps[ty * 8 + i][c0];
            #pragma unroll
            for (int cc = 0; cc < 4; cc++) {
                float4 va = *(const float4*)&sm->Vs[c0 + cc][tx * 8];
                float4 vb = *(const float4*)&sm->Vs[c0 + cc][tx * 8 + 4];
                float vr[8] = {va.x, va.y, va.z, va.w, vb.x, vb.y, vb.z, vb.w};
                #pragma unroll
                for (int i = 0; i < 8; i++) {
                    float p = (cc == 0) ? pv[i].x : (cc == 1) ? pv[i].y
                             : (cc == 2) ? pv[i].z : pv[i].w;
                    #pragma unroll
                    for (int j = 0; j < 8; j++)
                        o[i][j] = fmaf(p, vr[j], o[i][j]);
                }
            }
        }
    }

    // ---- epilogue: normalize by l, write (b,t,h,dv) ----
    #pragma unroll
    for (int i = 0; i < 8; i++) {
        float inv = 1.f / l[i];
        float* op = obuf + ((size_t)(b * SS + q0 + ty * 8 + i) * HH + h) * DVV + tx * 8;
        float4 v0 = make_float4(o[i][0] * inv, o[i][1] * inv, o[i][2] * inv, o[i][3] * inv);
        float4 v1 = make_float4(o[i][4] * inv, o[i][5] * inv, o[i][6] * inv, o[i][7] * inv);
        *(float4*)op = v0;
        *(float4*)(op + 4) = v1;
    }
}

// ---------------- combine: diff + RMSnorm + gamma ----------------
__global__ void combine_kernel(const float* __restrict__ o1, const float* __restrict__ o2,
                               const float* __restrict__ gamma, float* __restrict__ attn)
{
    int gtid = blockIdx.x * blockDim.x + threadIdx.x;
    int wid = gtid >> 5;       // (b*S + t)*H + h
    int lane = gtid & 31;
    float lam = g_lam;
    const float* p1 = o1 + (size_t)wid * DVV + lane * 4;
    const float* p2 = o2 + (size_t)wid * DVV + lane * 4;
    float4 a = *(const float4*)p1;
    float4 c2 = *(const float4*)p2;
    float4 d;
    d.x = a.x - lam * c2.x;
    d.y = a.y - lam * c2.y;
    d.z = a.z - lam * c2.z;
    d.w = a.w - lam * c2.w;
    float ss = d.x * d.x + d.y * d.y + d.z * d.z + d.w * d.w;
    #pragma unroll
    for (int off = 16; off; off >>= 1)
        ss += __shfl_xor_sync(0xffffffffu, ss, off);
    float r = rsqrtf(ss * (1.0f / DVV) + 1e-5f);
    float4 g = *(const float4*)(gamma + lane * 4);
    float sc = r * (1.0f - LAMBDA_INIT_F);
    float* op = attn + (size_t)(wid / HH) * EE + (wid % HH) * DVV + lane * 4;
    float4 outv = make_float4(d.x * sc * g.x, d.y * sc * g.y, d.z * sc * g.z, d.w * sc * g.w);
    *(float4*)op = outv;
}

// ---------------- launcher ----------------
extern "C" void kernel_launch(void* const* d_in, const int* in_sizes, int n_in,
                              void* d_out, int out_size)
{
    (void)in_sizes; (void)n_in; (void)out_size;
    const float* x   = (const float*)d_in[0];
    const float* Wq  = (const float*)d_in[1];
    const float* Wk  = (const float*)d_in[2];
    const float* Wv  = (const float*)d_in[3];
    const float* Wo  = (const float*)d_in[4];
    const float* lq1 = (const float*)d_in[5];
    const float* lk1 = (const float*)d_in[6];
    const float* lq2 = (const float*)d_in[7];
    const float* lk2 = (const float*)d_in[8];
    const float* gam = (const float*)d_in[9];
    float* out = (float*)d_out;

    float *pq, *pk, *pv, *po1, *po2, *pattn;
    cudaGetSymbolAddress((void**)&pq, g_q);
    cudaGetSymbolAddress((void**)&pk, g_k);
    cudaGetSymbolAddress((void**)&pv, g_v);
    cudaGetSymbolAddress((void**)&po1, g_o1);
    cudaGetSymbolAddress((void**)&po2, g_o2);
    cudaGetSymbolAddress((void**)&pattn, g_attn);

    cudaFuncSetAttribute(attn_kernel, cudaFuncAttributeMaxDynamicSharedMemorySize,
                         (int)sizeof(AttnSmem));

    dim3 gg(EE / 128, MTOKS / 128);   // (16, 32)
    gemm_mma<<<gg, 256>>>(x, Wq, pq, MTOKS, EE, EE);
    gemm_mma<<<gg, 256>>>(x, Wk, pk, MTOKS, EE, EE);
    gemm_mma<<<gg, 256>>>(x, Wv, pv, MTOKS, EE, EE);

    const int rope_total = MTOKS * CHN * (HDD / 2);
    rope_kernel<<<rope_total / 256, 256>>>(pq, pk);
    lambda_kernel<<<1, 32>>>(lq1, lk1, lq2, lk2);

    attn_kernel<<<dim3(SS / ABM, CHN, BB), 256, sizeof(AttnSmem)>>>(pq, pk, pv, po1, po2);

    combine_kernel<<<(BB * SS * HH * 32) / 256, 256>>>(po1, po2, gam, pattn);

    gemm_mma<<<gg, 256>>>(pattn, Wo, out, MTOKS, EE, EE);
}